// round 1
// baseline (speedup 1.0000x reference)
#include <cuda_runtime.h>
#include <cuda_bf16.h>
#include <cstdint>

#define NPAT 50000
#define NCON 20000
#define NN   70000
#define EE   800000
#define HH   128
#define LL   2

// ---------------- scratch (static device globals; no allocs allowed) ----------------
__device__ float g_buf0[(size_t)NN * HH];   // projection output / layer-0 input
__device__ float g_buf1[(size_t)NN * HH];   // layer-0 output / layer-1 input
__device__ float g_agg [(size_t)NN * HH];   // per-layer neighbor sum
__device__ float g_cnt [NN];
__device__ float g_rcnt[NN];

// ---------------- helpers ----------------
__device__ __forceinline__ void red_add_f4(float4* addr, float4 v) {
#if __CUDA_ARCH__ >= 900
    atomicAdd(addr, v);        // vector atomic (sm_90+), emitted as RED.128
#else
    float* f = (float*)addr;
    atomicAdd(f + 0, v.x); atomicAdd(f + 1, v.y);
    atomicAdd(f + 2, v.z); atomicAdd(f + 3, v.w);
#endif
}

// ---------------- per-relation in-degree (merged: ranges disjoint) ----------------
__global__ void count_kernel(const int* __restrict__ dst_pc,
                             const int* __restrict__ dst_cp,
                             float* __restrict__ cnt) {
    int i = blockIdx.x * blockDim.x + threadIdx.x;
    if (i < EE) {
        atomicAdd(&cnt[NPAT + dst_pc[i]], 1.0f);     // rel 0 -> concepts
    } else if (i < 2 * EE) {
        atomicAdd(&cnt[dst_cp[i - EE]], 1.0f);       // rel 1 -> patients
    }
}

__global__ void rcnt_kernel(const float* __restrict__ cnt, float* __restrict__ rcnt) {
    int i = blockIdx.x * blockDim.x + threadIdx.x;
    if (i < NN) rcnt[i] = 1.0f / fmaxf(cnt[i], 1.0f);
}

// ---------------- input projection: C[M,128] = A[M,K] @ W[K,128] + b ----------------
// 256 threads, 64-row tile; thread computes 8 rows x 4 cols.
template <int K>
__global__ void proj_kernel(const float* __restrict__ A, const float* __restrict__ W,
                            const float* __restrict__ bias, float* __restrict__ C, int M) {
    extern __shared__ float sm[];
    float* sW = sm;            // K x 128
    float* sA = sm + K * 128;  // 64 x K
    int tid = threadIdx.x;

    // load W (K*32 float4)
    float4* sW4 = (float4*)sW;
    const float4* Wg = (const float4*)W;
    for (int i = tid; i < K * 32; i += 256) sW4[i] = Wg[i];

    // load A tile: row = tid/4, quarter q = tid%4 covers K/4 floats
    {
        int row = tid >> 2, q = tid & 3;
        int r = blockIdx.x * 64 + row;
        const int f4p = K / 16;
        float4* dst = (float4*)(sA + row * K) + q * f4p;
        if (r < M) {
            const float4* Ar = (const float4*)(A + (size_t)r * K) + q * f4p;
#pragma unroll
            for (int i = 0; i < f4p; i++) dst[i] = Ar[i];
        } else {
#pragma unroll
            for (int i = 0; i < f4p; i++) dst[i] = make_float4(0.f, 0.f, 0.f, 0.f);
        }
    }
    __syncthreads();

    int rg = tid >> 5, cg = tid & 31;
    float4 acc[8];
#pragma unroll
    for (int i = 0; i < 8; i++) acc[i] = make_float4(0.f, 0.f, 0.f, 0.f);

#pragma unroll 4
    for (int k = 0; k < K; k++) {
        float4 w = sW4[k * 32 + cg];
#pragma unroll
        for (int i = 0; i < 8; i++) {
            float a = sA[(rg * 8 + i) * K + k];   // warp-broadcast
            acc[i].x += a * w.x; acc[i].y += a * w.y;
            acc[i].z += a * w.z; acc[i].w += a * w.w;
        }
    }

    float4 bb = ((const float4*)bias)[cg];
#pragma unroll
    for (int i = 0; i < 8; i++) {
        int r = blockIdx.x * 64 + rg * 8 + i;
        if (r < M) {
            float4 v = make_float4(acc[i].x + bb.x, acc[i].y + bb.y,
                                   acc[i].z + bb.z, acc[i].w + bb.w);
            ((float4*)(C + (size_t)r * HH))[cg] = v;
        }
    }
}

// ---------------- scatter: agg[dst] += x[src] for both relations ----------------
// One warp per edge, 32 x float4 = 128 floats.
__global__ void scatter_kernel(const float* __restrict__ X,
                               const int* __restrict__ src_pc, const int* __restrict__ dst_pc,
                               const int* __restrict__ src_cp, const int* __restrict__ dst_cp,
                               float* __restrict__ AGG) {
    long long t = (long long)blockIdx.x * blockDim.x + threadIdx.x;
    int w = (int)(t >> 5);
    if (w >= 2 * EE) return;
    int lane = threadIdx.x & 31;
    int s, d;
    if (w < EE) { s = src_pc[w];        d = NPAT + dst_pc[w]; }
    else        { s = NPAT + src_cp[w - EE]; d = dst_cp[w - EE]; }
    float4 v = ((const float4*)(X + (size_t)s * HH))[lane];
    red_add_f4(((float4*)(AGG + (size_t)d * HH)) + lane, v);
}

// ---------------- fused layer: out = relu([x | agg*rc] @ [Wroot;Wrel_sel] + b) ----------------
// K = 256. 256 threads, 64-row tile, thread computes 8 rows x 4 cols.
__global__ void layer_kernel(const float* __restrict__ X, const float* __restrict__ AGG,
                             const float* __restrict__ rcnt,
                             const float* __restrict__ Wroot, const float* __restrict__ brt,
                             const float* __restrict__ Wrel_pat, const float* __restrict__ Wrel_con,
                             float* __restrict__ C) {
    extern __shared__ float sm[];
    float* sW = sm;              // 256 x 128
    float* sA = sm + 256 * 128;  // 64 x 256
    const int NBP = (NPAT + 63) / 64;  // 782
    int bid = blockIdx.x;
    int base, rowlim;
    const float* Wrel;
    if (bid < NBP) { base = bid * 64;                 Wrel = Wrel_pat; rowlim = NPAT; }
    else           { base = NPAT + (bid - NBP) * 64;  Wrel = Wrel_con; rowlim = NN; }

    int tid = threadIdx.x;
    float4* sW4 = (float4*)sW;
    {
        const float4* Wr = (const float4*)Wroot;
        const float4* Wl = (const float4*)Wrel;
        for (int i = tid; i < 128 * 32; i += 256) sW4[i] = Wr[i];
        for (int i = tid; i < 128 * 32; i += 256) sW4[128 * 32 + i] = Wl[i];
    }
    // A tile: row = tid/4, q = tid%4 covers 64 cols (16 float4) of the 256-wide row
    {
        int row = tid >> 2, q = tid & 3;
        int r = base + row;
        float4* dst = (float4*)(sA + row * 256) + q * 16;
        if (r < rowlim) {
            float rc = rcnt[r];
            const float4* xr = (const float4*)(X   + (size_t)r * HH);
            const float4* ar = (const float4*)(AGG + (size_t)r * HH);
#pragma unroll
            for (int i = 0; i < 16; i++) {
                int c4 = q * 16 + i;
                float4 v;
                if (c4 < 32) v = xr[c4];
                else { float4 a = ar[c4 - 32]; v = make_float4(a.x*rc, a.y*rc, a.z*rc, a.w*rc); }
                dst[i] = v;
            }
        } else {
#pragma unroll
            for (int i = 0; i < 16; i++) dst[i] = make_float4(0.f, 0.f, 0.f, 0.f);
        }
    }
    __syncthreads();

    int rg = tid >> 5, cg = tid & 31;
    float4 acc[8];
#pragma unroll
    for (int i = 0; i < 8; i++) acc[i] = make_float4(0.f, 0.f, 0.f, 0.f);

#pragma unroll 4
    for (int k = 0; k < 256; k++) {
        float4 w = sW4[k * 32 + cg];
#pragma unroll
        for (int i = 0; i < 8; i++) {
            float a = sA[(rg * 8 + i) * 256 + k];  // warp-broadcast
            acc[i].x += a * w.x; acc[i].y += a * w.y;
            acc[i].z += a * w.z; acc[i].w += a * w.w;
        }
    }

    float4 bb = ((const float4*)brt)[cg];
#pragma unroll
    for (int i = 0; i < 8; i++) {
        int r = base + rg * 8 + i;
        if (r < rowlim) {
            float4 v;
            v.x = fmaxf(acc[i].x + bb.x, 0.f);
            v.y = fmaxf(acc[i].y + bb.y, 0.f);
            v.z = fmaxf(acc[i].z + bb.z, 0.f);
            v.w = fmaxf(acc[i].w + bb.w, 0.f);
            ((float4*)(C + (size_t)r * HH))[cg] = v;
        }
    }
}

// ---------------- launch ----------------
extern "C" void kernel_launch(void* const* d_in, const int* in_sizes, int n_in,
                              void* d_out, int out_size) {
    const float* x_patient = (const float*)d_in[0];
    const float* x_concept = (const float*)d_in[1];
    const float* W_p    = (const float*)d_in[2];
    const float* b_p    = (const float*)d_in[3];
    const float* W_c    = (const float*)d_in[4];
    const float* b_c    = (const float*)d_in[5];
    const float* W_root = (const float*)d_in[6];
    const float* b_root = (const float*)d_in[7];
    const float* W_rel  = (const float*)d_in[8];
    const int* src_pc = (const int*)d_in[9];
    const int* dst_pc = (const int*)d_in[10];
    const int* src_cp = (const int*)d_in[11];
    const int* dst_cp = (const int*)d_in[12];
    float* out = (float*)d_out;

    float *buf0, *buf1, *agg, *cnt, *rcnt;
    cudaGetSymbolAddress((void**)&buf0, g_buf0);
    cudaGetSymbolAddress((void**)&buf1, g_buf1);
    cudaGetSymbolAddress((void**)&agg,  g_agg);
    cudaGetSymbolAddress((void**)&cnt,  g_cnt);
    cudaGetSymbolAddress((void**)&rcnt, g_rcnt);

    const int LAYER_SMEM  = (256 * 128 + 64 * 256) * 4;  // 192 KB
    const int PROJ64_SMEM  = (64  * 128 + 64 * 64 ) * 4; // 48 KB
    const int PROJ128_SMEM = (128 * 128 + 64 * 128) * 4; // 96 KB
    cudaFuncSetAttribute(layer_kernel, cudaFuncAttributeMaxDynamicSharedMemorySize, LAYER_SMEM);
    cudaFuncSetAttribute(proj_kernel<64>,  cudaFuncAttributeMaxDynamicSharedMemorySize, PROJ64_SMEM);
    cudaFuncSetAttribute(proj_kernel<128>, cudaFuncAttributeMaxDynamicSharedMemorySize, PROJ128_SMEM);

    // counts (once per call)
    cudaMemsetAsync(cnt, 0, NN * sizeof(float));
    count_kernel<<<(2 * EE + 255) / 256, 256>>>(dst_pc, dst_cp, cnt);
    rcnt_kernel<<<(NN + 255) / 256, 256>>>(cnt, rcnt);

    // projections into buf0
    proj_kernel<64><<<(NPAT + 63) / 64, 256, PROJ64_SMEM>>>(x_patient, W_p, b_p, buf0, NPAT);
    proj_kernel<128><<<(NCON + 63) / 64, 256, PROJ128_SMEM>>>(x_concept, W_c, b_c,
                                                              buf0 + (size_t)NPAT * HH, NCON);

    const int NB = (NPAT + 63) / 64 + (NCON + 63) / 64;  // 782 + 313 = 1095
    const int SCATTER_BLOCKS = (2 * EE) / 8;             // 8 warps/block, 1 warp/edge

    for (int l = 0; l < LL; l++) {
        const float* in  = (l == 0) ? buf0 : buf1;
        float*       dst = (l == 0) ? buf1 : out;
        cudaMemsetAsync(agg, 0, (size_t)NN * HH * sizeof(float));
        scatter_kernel<<<SCATTER_BLOCKS, 256>>>(in, src_pc, dst_pc, src_cp, dst_cp, agg);
        layer_kernel<<<NB, 256, LAYER_SMEM>>>(
            in, agg, rcnt,
            W_root + (size_t)l * HH * HH,
            b_root + (size_t)l * HH,
            W_rel + ((size_t)l * 2 + 1) * HH * HH,   // rel 1 -> patient rows
            W_rel + ((size_t)l * 2 + 0) * HH * HH,   // rel 0 -> concept rows
            dst);
    }
}

// round 2
// speedup vs baseline: 1.2915x; 1.2915x over previous
#include <cuda_runtime.h>
#include <cuda_bf16.h>
#include <cstdint>

#define NPAT 50000
#define NCON 20000
#define NN   70000
#define EE   800000
#define HH   128
#define LL   2

// ---------------- scratch (static device globals; no allocs allowed) ----------------
__device__ float g_buf0[(size_t)NN * HH];   // projection output / layer-0 input
__device__ float g_buf1[(size_t)NN * HH];   // layer-0 output / layer-1 input
__device__ float g_agg [(size_t)NN * HH];   // per-layer normalized neighbor mean
__device__ int   g_deg [NN];
__device__ float g_rcnt[NN];
__device__ int   g_off [NN + 1];
__device__ int   g_cur [NN];
__device__ int   g_csr [2 * EE];

// ---------------- degree histogram (relations disjoint: merged node space) ----------
__global__ void deg_kernel(const int* __restrict__ dst_pc,
                           const int* __restrict__ dst_cp,
                           int* __restrict__ deg) {
    int i = blockIdx.x * blockDim.x + threadIdx.x;
    if (i < EE) {
        atomicAdd(&deg[NPAT + dst_pc[i]], 1);     // rel 0 -> concepts
    } else if (i < 2 * EE) {
        atomicAdd(&deg[dst_cp[i - EE]], 1);       // rel 1 -> patients
    }
}

__global__ void rcnt_kernel(const int* __restrict__ deg, float* __restrict__ rcnt) {
    int i = blockIdx.x * blockDim.x + threadIdx.x;
    if (i < NN) rcnt[i] = 1.0f / (float)max(deg[i], 1);
}

// ---------------- single-block exclusive scan over NN degrees -----------------------
__global__ void scan_kernel(const int* __restrict__ deg, int* __restrict__ off) {
    __shared__ int ssum[1024];
    int tid = threadIdx.x;
    const int PER = (NN + 1023) / 1024;   // 69
    int base = tid * PER;
    int s = 0;
    for (int i = 0; i < PER; i++) {
        int idx = base + i;
        if (idx < NN) s += deg[idx];
    }
    ssum[tid] = s;
    __syncthreads();
    // inclusive Hillis-Steele scan
    for (int ofs = 1; ofs < 1024; ofs <<= 1) {
        int v = (tid >= ofs) ? ssum[tid - ofs] : 0;
        __syncthreads();
        ssum[tid] += v;
        __syncthreads();
    }
    int run = (tid == 0) ? 0 : ssum[tid - 1];   // exclusive prefix
    for (int i = 0; i < PER; i++) {
        int idx = base + i;
        if (idx < NN) { off[idx] = run; run += deg[idx]; }
    }
    if (tid == 0) off[NN] = ssum[1023];
}

// ---------------- CSR fill (order within a node is arbitrary; fp-sum jitter ~1e-7) --
__global__ void fill_kernel(const int* __restrict__ src_pc, const int* __restrict__ dst_pc,
                            const int* __restrict__ src_cp, const int* __restrict__ dst_cp,
                            const int* __restrict__ off, int* __restrict__ cur,
                            int* __restrict__ csr) {
    int i = blockIdx.x * blockDim.x + threadIdx.x;
    int s, d;
    if (i < EE)          { s = src_pc[i];             d = NPAT + dst_pc[i]; }
    else if (i < 2 * EE) { s = NPAT + src_cp[i - EE]; d = dst_cp[i - EE]; }
    else return;
    int pos = off[d] + atomicAdd(&cur[d], 1);
    csr[pos] = s;
}

// ---------------- gather-aggregate: agg[d] = (sum_{e in CSR(d)} x[src_e]) * rcnt[d] -
__global__ void gather_kernel(const float* __restrict__ X,
                              const int* __restrict__ off, const int* __restrict__ csr,
                              const float* __restrict__ rcnt, float* __restrict__ AGG) {
    int warp = (int)((blockIdx.x * (long long)blockDim.x + threadIdx.x) >> 5);
    if (warp >= NN) return;
    int lane = threadIdx.x & 31;
    int beg = off[warp], end = off[warp + 1];
    float4 acc = make_float4(0.f, 0.f, 0.f, 0.f);

    int e = beg;
    for (; e + 32 <= end; e += 32) {
        int idx = csr[e + lane];
#pragma unroll
        for (int j = 0; j < 32; j++) {
            int s = __shfl_sync(0xffffffffu, idx, j);
            float4 v = ((const float4*)(X + (size_t)s * HH))[lane];
            acc.x += v.x; acc.y += v.y; acc.z += v.z; acc.w += v.w;
        }
    }
    int rem = end - e;
    if (rem > 0) {
        int idx = (lane < rem) ? csr[e + lane] : 0;
        for (int j = 0; j < rem; j++) {
            int s = __shfl_sync(0xffffffffu, idx, j);
            float4 v = ((const float4*)(X + (size_t)s * HH))[lane];
            acc.x += v.x; acc.y += v.y; acc.z += v.z; acc.w += v.w;
        }
    }
    float rc = rcnt[warp];
    ((float4*)(AGG + (size_t)warp * HH))[lane] =
        make_float4(acc.x * rc, acc.y * rc, acc.z * rc, acc.w * rc);
}

// ---------------- input projection: C[M,128] = A[M,K] @ W[K,128] + b ----------------
template <int K>
__global__ void proj_kernel(const float* __restrict__ A, const float* __restrict__ W,
                            const float* __restrict__ bias, float* __restrict__ C, int M) {
    extern __shared__ float sm[];
    float* sW = sm;            // K x 128
    float* sA = sm + K * 128;  // 64 x K
    int tid = threadIdx.x;

    float4* sW4 = (float4*)sW;
    const float4* Wg = (const float4*)W;
    for (int i = tid; i < K * 32; i += 256) sW4[i] = Wg[i];

    {
        int row = tid >> 2, q = tid & 3;
        int r = blockIdx.x * 64 + row;
        const int f4p = K / 16;
        float4* dst = (float4*)(sA + row * K) + q * f4p;
        if (r < M) {
            const float4* Ar = (const float4*)(A + (size_t)r * K) + q * f4p;
#pragma unroll
            for (int i = 0; i < f4p; i++) dst[i] = Ar[i];
        } else {
#pragma unroll
            for (int i = 0; i < f4p; i++) dst[i] = make_float4(0.f, 0.f, 0.f, 0.f);
        }
    }
    __syncthreads();

    int rg = tid >> 5, cg = tid & 31;
    float4 acc[8];
#pragma unroll
    for (int i = 0; i < 8; i++) acc[i] = make_float4(0.f, 0.f, 0.f, 0.f);

    const float4* sA4 = (const float4*)sA;
#pragma unroll 2
    for (int k4 = 0; k4 < K / 4; k4++) {
        float4 w0 = sW4[(4 * k4 + 0) * 32 + cg];
        float4 w1 = sW4[(4 * k4 + 1) * 32 + cg];
        float4 w2 = sW4[(4 * k4 + 2) * 32 + cg];
        float4 w3 = sW4[(4 * k4 + 3) * 32 + cg];
#pragma unroll
        for (int i = 0; i < 8; i++) {
            float4 a = sA4[(rg * 8 + i) * (K / 4) + k4];
            acc[i].x += a.x * w0.x + a.y * w1.x + a.z * w2.x + a.w * w3.x;
            acc[i].y += a.x * w0.y + a.y * w1.y + a.z * w2.y + a.w * w3.y;
            acc[i].z += a.x * w0.z + a.y * w1.z + a.z * w2.z + a.w * w3.z;
            acc[i].w += a.x * w0.w + a.y * w1.w + a.z * w2.w + a.w * w3.w;
        }
    }

    float4 bb = ((const float4*)bias)[cg];
#pragma unroll
    for (int i = 0; i < 8; i++) {
        int r = blockIdx.x * 64 + rg * 8 + i;
        if (r < M) {
            float4 v = make_float4(acc[i].x + bb.x, acc[i].y + bb.y,
                                   acc[i].z + bb.z, acc[i].w + bb.w);
            ((float4*)(C + (size_t)r * HH))[cg] = v;
        }
    }
}

// ---------------- fused layer: out = relu([x | agg] @ [Wroot;Wrel_sel] + b) ---------
__global__ void layer_kernel(const float* __restrict__ X, const float* __restrict__ AGG,
                             const float* __restrict__ Wroot, const float* __restrict__ brt,
                             const float* __restrict__ Wrel_pat, const float* __restrict__ Wrel_con,
                             float* __restrict__ C) {
    extern __shared__ float sm[];
    float* sW = sm;              // 256 x 128
    float* sA = sm + 256 * 128;  // 64 x 256
    const int NBP = (NPAT + 63) / 64;  // 782
    int bid = blockIdx.x;
    int base, rowlim;
    const float* Wrel;
    if (bid < NBP) { base = bid * 64;                 Wrel = Wrel_pat; rowlim = NPAT; }
    else           { base = NPAT + (bid - NBP) * 64;  Wrel = Wrel_con; rowlim = NN; }

    int tid = threadIdx.x;
    float4* sW4 = (float4*)sW;
    {
        const float4* Wr = (const float4*)Wroot;
        const float4* Wl = (const float4*)Wrel;
        for (int i = tid; i < 128 * 32; i += 256) sW4[i] = Wr[i];
        for (int i = tid; i < 128 * 32; i += 256) sW4[128 * 32 + i] = Wl[i];
    }
    {
        int row = tid >> 2, q = tid & 3;
        int r = base + row;
        float4* dst = (float4*)(sA + row * 256) + q * 16;
        if (r < rowlim) {
            const float4* xr = (const float4*)(X   + (size_t)r * HH);
            const float4* ar = (const float4*)(AGG + (size_t)r * HH);
#pragma unroll
            for (int i = 0; i < 16; i++) {
                int c4 = q * 16 + i;
                dst[i] = (c4 < 32) ? xr[c4] : ar[c4 - 32];
            }
        } else {
#pragma unroll
            for (int i = 0; i < 16; i++) dst[i] = make_float4(0.f, 0.f, 0.f, 0.f);
        }
    }
    __syncthreads();

    int rg = tid >> 5, cg = tid & 31;
    float4 acc[8];
#pragma unroll
    for (int i = 0; i < 8; i++) acc[i] = make_float4(0.f, 0.f, 0.f, 0.f);

    const float4* sA4 = (const float4*)sA;
#pragma unroll 2
    for (int k4 = 0; k4 < 64; k4++) {
        float4 w0 = sW4[(4 * k4 + 0) * 32 + cg];
        float4 w1 = sW4[(4 * k4 + 1) * 32 + cg];
        float4 w2 = sW4[(4 * k4 + 2) * 32 + cg];
        float4 w3 = sW4[(4 * k4 + 3) * 32 + cg];
#pragma unroll
        for (int i = 0; i < 8; i++) {
            float4 a = sA4[(rg * 8 + i) * 64 + k4];
            acc[i].x += a.x * w0.x + a.y * w1.x + a.z * w2.x + a.w * w3.x;
            acc[i].y += a.x * w0.y + a.y * w1.y + a.z * w2.y + a.w * w3.y;
            acc[i].z += a.x * w0.z + a.y * w1.z + a.z * w2.z + a.w * w3.z;
            acc[i].w += a.x * w0.w + a.y * w1.w + a.z * w2.w + a.w * w3.w;
        }
    }

    float4 bb = ((const float4*)brt)[cg];
#pragma unroll
    for (int i = 0; i < 8; i++) {
        int r = base + rg * 8 + i;
        if (r < rowlim) {
            float4 v;
            v.x = fmaxf(acc[i].x + bb.x, 0.f);
            v.y = fmaxf(acc[i].y + bb.y, 0.f);
            v.z = fmaxf(acc[i].z + bb.z, 0.f);
            v.w = fmaxf(acc[i].w + bb.w, 0.f);
            ((float4*)(C + (size_t)r * HH))[cg] = v;
        }
    }
}

// ---------------- launch ----------------
extern "C" void kernel_launch(void* const* d_in, const int* in_sizes, int n_in,
                              void* d_out, int out_size) {
    const float* x_patient = (const float*)d_in[0];
    const float* x_concept = (const float*)d_in[1];
    const float* W_p    = (const float*)d_in[2];
    const float* b_p    = (const float*)d_in[3];
    const float* W_c    = (const float*)d_in[4];
    const float* b_c    = (const float*)d_in[5];
    const float* W_root = (const float*)d_in[6];
    const float* b_root = (const float*)d_in[7];
    const float* W_rel  = (const float*)d_in[8];
    const int* src_pc = (const int*)d_in[9];
    const int* dst_pc = (const int*)d_in[10];
    const int* src_cp = (const int*)d_in[11];
    const int* dst_cp = (const int*)d_in[12];
    float* out = (float*)d_out;

    float *buf0, *buf1, *agg, *rcnt;
    int *deg, *off, *cur, *csr;
    cudaGetSymbolAddress((void**)&buf0, g_buf0);
    cudaGetSymbolAddress((void**)&buf1, g_buf1);
    cudaGetSymbolAddress((void**)&agg,  g_agg);
    cudaGetSymbolAddress((void**)&rcnt, g_rcnt);
    cudaGetSymbolAddress((void**)&deg,  g_deg);
    cudaGetSymbolAddress((void**)&off,  g_off);
    cudaGetSymbolAddress((void**)&cur,  g_cur);
    cudaGetSymbolAddress((void**)&csr,  g_csr);

    const int LAYER_SMEM   = (256 * 128 + 64 * 256) * 4;  // 192 KB
    const int PROJ64_SMEM  = (64  * 128 + 64 * 64 ) * 4;  // 48 KB
    const int PROJ128_SMEM = (128 * 128 + 64 * 128) * 4;  // 96 KB
    cudaFuncSetAttribute(layer_kernel, cudaFuncAttributeMaxDynamicSharedMemorySize, LAYER_SMEM);
    cudaFuncSetAttribute(proj_kernel<64>,  cudaFuncAttributeMaxDynamicSharedMemorySize, PROJ64_SMEM);
    cudaFuncSetAttribute(proj_kernel<128>, cudaFuncAttributeMaxDynamicSharedMemorySize, PROJ128_SMEM);

    // ---- CSR build (once per call, reused by both layers) ----
    cudaMemsetAsync(deg, 0, NN * sizeof(int));
    cudaMemsetAsync(cur, 0, NN * sizeof(int));
    deg_kernel<<<(2 * EE + 255) / 256, 256>>>(dst_pc, dst_cp, deg);
    scan_kernel<<<1, 1024>>>(deg, off);
    rcnt_kernel<<<(NN + 255) / 256, 256>>>(deg, rcnt);
    fill_kernel<<<(2 * EE + 255) / 256, 256>>>(src_pc, dst_pc, src_cp, dst_cp, off, cur, csr);

    // ---- projections into buf0 ----
    proj_kernel<64><<<(NPAT + 63) / 64, 256, PROJ64_SMEM>>>(x_patient, W_p, b_p, buf0, NPAT);
    proj_kernel<128><<<(NCON + 63) / 64, 256, PROJ128_SMEM>>>(x_concept, W_c, b_c,
                                                              buf0 + (size_t)NPAT * HH, NCON);

    const int NB = (NPAT + 63) / 64 + (NCON + 63) / 64;  // 1095
    const int GATHER_BLOCKS = (NN + 7) / 8;              // 8 warps/block, warp/node

    for (int l = 0; l < LL; l++) {
        const float* in  = (l == 0) ? buf0 : buf1;
        float*       dst = (l == 0) ? buf1 : out;
        gather_kernel<<<GATHER_BLOCKS, 256>>>(in, off, csr, rcnt, agg);
        layer_kernel<<<NB, 256, LAYER_SMEM>>>(
            in, agg,
            W_root + (size_t)l * HH * HH,
            b_root + (size_t)l * HH,
            W_rel + ((size_t)l * 2 + 1) * HH * HH,   // rel 1 -> patient rows
            W_rel + ((size_t)l * 2 + 0) * HH * HH,   // rel 0 -> concept rows
            dst);
    }
}

// round 4
// speedup vs baseline: 1.9178x; 1.4850x over previous
#include <cuda_runtime.h>
#include <cuda_bf16.h>
#include <cstdint>

#define NPAT 50000
#define NCON 20000
#define NN   70000
#define EE   800000
#define HH   128
#define LL   2

// ---------------- scratch (static device globals; no allocs allowed) ----------------
__device__ float g_buf0[(size_t)NN * HH];
__device__ float g_buf1[(size_t)NN * HH];
__device__ float g_agg [(size_t)NN * HH];
__device__ int   g_deg [NN];
__device__ float g_rcnt[NN];
__device__ int   g_off [NN + 1];
__device__ int   g_cur [NN];
__device__ int   g_csr [2 * EE];
// pre-transposed/split weights: [variant(4)*split(2)][k(256)][n(128)]
__device__ float g_B[(size_t)8 * 256 * 128];

// ---------------- helpers ----------------
__device__ __forceinline__ float cvt_tf32(float v) {
    float h; asm("cvt.rna.tf32.f32 %0, %1;" : "=f"(h) : "f"(v)); return h;
}

__device__ __forceinline__ void mma_tf32(float* c, const uint32_t* a, const uint32_t* b) {
    asm volatile(
        "mma.sync.aligned.m16n8k8.row.col.f32.tf32.tf32.f32 "
        "{%0,%1,%2,%3}, {%4,%5,%6,%7}, {%8,%9}, {%0,%1,%2,%3};"
        : "+f"(c[0]), "+f"(c[1]), "+f"(c[2]), "+f"(c[3])
        : "r"(a[0]), "r"(a[1]), "r"(a[2]), "r"(a[3]),
          "r"(b[0]), "r"(b[1]));
}

// ---------------- degree histogram ----------------
__global__ void deg_kernel(const int* __restrict__ dst_pc, const int* __restrict__ dst_cp,
                           int* __restrict__ deg) {
    int i = blockIdx.x * blockDim.x + threadIdx.x;
    if (i < EE)               atomicAdd(&deg[NPAT + dst_pc[i]], 1);
    else if (i < 2 * EE)      atomicAdd(&deg[dst_cp[i - EE]], 1);
}

__global__ void rcnt_kernel(const int* __restrict__ deg, float* __restrict__ rcnt) {
    int i = blockIdx.x * blockDim.x + threadIdx.x;
    if (i < NN) rcnt[i] = 1.0f / (float)max(deg[i], 1);
}

// ---------------- single-block exclusive scan ----------------
__global__ void scan_kernel(const int* __restrict__ deg, int* __restrict__ off) {
    __shared__ int ssum[1024];
    int tid = threadIdx.x;
    const int PER = (NN + 1023) / 1024;
    int base = tid * PER;
    int s = 0;
    for (int i = 0; i < PER; i++) { int idx = base + i; if (idx < NN) s += deg[idx]; }
    ssum[tid] = s;
    __syncthreads();
    for (int ofs = 1; ofs < 1024; ofs <<= 1) {
        int v = (tid >= ofs) ? ssum[tid - ofs] : 0;
        __syncthreads();
        ssum[tid] += v;
        __syncthreads();
    }
    int run = (tid == 0) ? 0 : ssum[tid - 1];
    for (int i = 0; i < PER; i++) {
        int idx = base + i;
        if (idx < NN) { off[idx] = run; run += deg[idx]; }
    }
    if (tid == 0) off[NN] = ssum[1023];
}

// ---------------- CSR fill ----------------
__global__ void fill_kernel(const int* __restrict__ src_pc, const int* __restrict__ dst_pc,
                            const int* __restrict__ src_cp, const int* __restrict__ dst_cp,
                            const int* __restrict__ off, int* __restrict__ cur,
                            int* __restrict__ csr) {
    int i = blockIdx.x * blockDim.x + threadIdx.x;
    int s, d;
    if (i < EE)          { s = src_pc[i];             d = NPAT + dst_pc[i]; }
    else if (i < 2 * EE) { s = NPAT + src_cp[i - EE]; d = dst_cp[i - EE]; }
    else return;
    int pos = off[d] + atomicAdd(&cur[d], 1);
    csr[pos] = s;
}

// ---------------- gather-aggregate ----------------
__global__ void gather_kernel(const float* __restrict__ X,
                              const int* __restrict__ off, const int* __restrict__ csr,
                              const float* __restrict__ rcnt, float* __restrict__ AGG) {
    int warp = (int)((blockIdx.x * (long long)blockDim.x + threadIdx.x) >> 5);
    if (warp >= NN) return;
    int lane = threadIdx.x & 31;
    int beg = off[warp], end = off[warp + 1];
    float4 acc = make_float4(0.f, 0.f, 0.f, 0.f);
    int e = beg;
    for (; e + 32 <= end; e += 32) {
        int idx = csr[e + lane];
#pragma unroll
        for (int j = 0; j < 32; j++) {
            int s = __shfl_sync(0xffffffffu, idx, j);
            float4 v = ((const float4*)(X + (size_t)s * HH))[lane];
            acc.x += v.x; acc.y += v.y; acc.z += v.z; acc.w += v.w;
        }
    }
    int rem = end - e;
    if (rem > 0) {
        int idx = (lane < rem) ? csr[e + lane] : 0;
        for (int j = 0; j < rem; j++) {
            int s = __shfl_sync(0xffffffffu, idx, j);
            float4 v = ((const float4*)(X + (size_t)s * HH))[lane];
            acc.x += v.x; acc.y += v.y; acc.z += v.z; acc.w += v.w;
        }
    }
    float rc = rcnt[warp];
    ((float4*)(AGG + (size_t)warp * HH))[lane] =
        make_float4(acc.x * rc, acc.y * rc, acc.z * rc, acc.w * rc);
}

// ---------------- input projection (FFMA): C[M,128] = A[M,K] @ W[K,128] + b ---------
template <int K>
__global__ void proj_kernel(const float* __restrict__ A, const float* __restrict__ W,
                            const float* __restrict__ bias, float* __restrict__ C, int M) {
    extern __shared__ float sm[];
    float* sW = sm;
    float* sA = sm + K * 128;
    int tid = threadIdx.x;

    float4* sW4 = (float4*)sW;
    const float4* Wg = (const float4*)W;
    for (int i = tid; i < K * 32; i += 256) sW4[i] = Wg[i];
    {
        int row = tid >> 2, q = tid & 3;
        int r = blockIdx.x * 64 + row;
        const int f4p = K / 16;
        float4* dst = (float4*)(sA + row * K) + q * f4p;
        if (r < M) {
            const float4* Ar = (const float4*)(A + (size_t)r * K) + q * f4p;
#pragma unroll
            for (int i = 0; i < f4p; i++) dst[i] = Ar[i];
        } else {
#pragma unroll
            for (int i = 0; i < f4p; i++) dst[i] = make_float4(0.f, 0.f, 0.f, 0.f);
        }
    }
    __syncthreads();

    int rg = tid >> 5, cg = tid & 31;
    float4 acc[8];
#pragma unroll
    for (int i = 0; i < 8; i++) acc[i] = make_float4(0.f, 0.f, 0.f, 0.f);
    const float4* sA4 = (const float4*)sA;
#pragma unroll 2
    for (int k4 = 0; k4 < K / 4; k4++) {
        float4 w0 = sW4[(4 * k4 + 0) * 32 + cg];
        float4 w1 = sW4[(4 * k4 + 1) * 32 + cg];
        float4 w2 = sW4[(4 * k4 + 2) * 32 + cg];
        float4 w3 = sW4[(4 * k4 + 3) * 32 + cg];
#pragma unroll
        for (int i = 0; i < 8; i++) {
            float4 a = sA4[(rg * 8 + i) * (K / 4) + k4];
            acc[i].x += a.x * w0.x + a.y * w1.x + a.z * w2.x + a.w * w3.x;
            acc[i].y += a.x * w0.y + a.y * w1.y + a.z * w2.y + a.w * w3.y;
            acc[i].z += a.x * w0.z + a.y * w1.z + a.z * w2.z + a.w * w3.z;
            acc[i].w += a.x * w0.w + a.y * w1.w + a.z * w2.w + a.w * w3.w;
        }
    }
    float4 bb = ((const float4*)bias)[cg];
#pragma unroll
    for (int i = 0; i < 8; i++) {
        int r = blockIdx.x * 64 + rg * 8 + i;
        if (r < M) {
            float4 v = make_float4(acc[i].x + bb.x, acc[i].y + bb.y,
                                   acc[i].z + bb.z, acc[i].w + bb.w);
            ((float4*)(C + (size_t)r * HH))[cg] = v;
        }
    }
}

// ---------------- weight prep: transpose + tf32-split ------------------------------
// variant v: l = v>>1, type = v&1 (0 = patient rows -> [Wroot;Wrel[1]]; 1 = concept -> Wrel[0])
__global__ void prepB_kernel(const float* __restrict__ W_root, const float* __restrict__ W_rel,
                             float* __restrict__ B) {
    int i = blockIdx.x * blockDim.x + threadIdx.x;
    if (i >= 4 * 256 * 128) return;
    int n = i & 127;
    int k = (i >> 7) & 255;
    int v = i >> 15;
    int l = v >> 1, type = v & 1;
    float val;
    if (k < 128) {
        val = W_root[((size_t)l * 128 + k) * 128 + n];
    } else {
        int rel = (type == 0) ? 1 : 0;
        val = W_rel[(((size_t)l * 2 + rel) * 128 + (k - 128)) * 128 + n];
    }
    float hi = cvt_tf32(val);
    float lo = val - hi;
    B[(((size_t)(v * 2 + 0)) * 256 + k) * 128 + n] = hi;
    B[(((size_t)(v * 2 + 1)) * 256 + k) * 128 + n] = lo;
}

// ---------------- mma.sync tf32 layer: out = relu([x|agg] @ Bv + b) ------------------
// CTA: M=128, N=128, K=256 in 8 chunks of 32. 8 warps: warpM = wid&3, warpN = wid>>2.
// smem strides: A 36 floats/row (pad 4), B 136 floats/row (pad 8) -> conflict-free frags.
#define ASTR 36
#define BSTR 136
#define SM_AHI 0
#define SM_ALO (128 * ASTR)
#define SM_BHI (2 * 128 * ASTR)
#define SM_BLO (2 * 128 * ASTR + 32 * BSTR)
#define SM_FLOATS (2 * 128 * ASTR + 2 * 32 * BSTR)

__global__ void __launch_bounds__(256, 2)
layer_mma_kernel(const float* __restrict__ X, const float* __restrict__ AGG,
                 const float* __restrict__ Bglob, const float* __restrict__ bias,
                 float* __restrict__ C, int layer) {
    extern __shared__ float sm[];
    int tid = threadIdx.x, wid = tid >> 5, lane = tid & 31;
    int warpM = wid & 3, warpN = wid >> 2;

    const int NBP_T = (NPAT + 127) / 128;   // 391
    int bid = blockIdx.x;
    int base, rowlim, v;
    if (bid < NBP_T) { base = bid * 128;                  rowlim = NPAT; v = layer * 2; }
    else             { base = NPAT + (bid - NBP_T) * 128; rowlim = NN;   v = layer * 2 + 1; }

    float acc[2][8][4];
#pragma unroll
    for (int mt = 0; mt < 2; mt++)
#pragma unroll
        for (int nt = 0; nt < 8; nt++)
#pragma unroll
            for (int r = 0; r < 4; r++) acc[mt][nt][r] = 0.f;

    int arow = tid >> 1;                 // 2 threads per row
    int node = base + arow;
    bool valid = node < rowlim;
    int f4base = (tid & 1) * 4;          // float4 index within 32-float row segment

    for (int chunk = 0; chunk < 8; chunk++) {
        // ---- A chunk: load, split hi/lo ----
        const float* src = (chunk < 4)
            ? (X   + (size_t)node * HH + chunk * 32)
            : (AGG + (size_t)node * HH + (chunk - 4) * 32);
#pragma unroll
        for (int i = 0; i < 4; i++) {
            int f4 = f4base + i;
            float4 a = valid ? ((const float4*)src)[f4] : make_float4(0.f, 0.f, 0.f, 0.f);
            float4 hi4, lo4;
            hi4.x = cvt_tf32(a.x); lo4.x = a.x - hi4.x;
            hi4.y = cvt_tf32(a.y); lo4.y = a.y - hi4.y;
            hi4.z = cvt_tf32(a.z); lo4.z = a.z - hi4.z;
            hi4.w = cvt_tf32(a.w); lo4.w = a.w - hi4.w;
            *(float4*)&sm[SM_AHI + arow * ASTR + f4 * 4] = hi4;
            *(float4*)&sm[SM_ALO + arow * ASTR + f4 * 4] = lo4;
        }
        // ---- B chunk copy: 32x128 floats per split ----
        {
            const float4* bh = (const float4*)(Bglob + (((size_t)(v * 2 + 0)) * 256 + chunk * 32) * 128);
            const float4* bl = (const float4*)(Bglob + (((size_t)(v * 2 + 1)) * 256 + chunk * 32) * 128);
#pragma unroll
            for (int i = 0; i < 4; i++) {
                int idx = tid + 256 * i;          // < 1024
                int kk = idx >> 5, n4 = idx & 31;
                *(float4*)&sm[SM_BHI + kk * BSTR + n4 * 4] = bh[idx];
                *(float4*)&sm[SM_BLO + kk * BSTR + n4 * 4] = bl[idx];
            }
        }
        __syncthreads();

        // ---- mma over 4 k8-steps ----
#pragma unroll
        for (int k8 = 0; k8 < 4; k8++) {
            int k0 = k8 * 8;
            uint32_t ah[2][4], al[2][4];
#pragma unroll
            for (int mt = 0; mt < 2; mt++) {
                int r0 = warpM * 32 + mt * 16 + (lane >> 2);
                int c0 = k0 + (lane & 3);
                ah[mt][0] = __float_as_uint(sm[SM_AHI + r0 * ASTR + c0]);
                ah[mt][1] = __float_as_uint(sm[SM_AHI + (r0 + 8) * ASTR + c0]);
                ah[mt][2] = __float_as_uint(sm[SM_AHI + r0 * ASTR + c0 + 4]);
                ah[mt][3] = __float_as_uint(sm[SM_AHI + (r0 + 8) * ASTR + c0 + 4]);
                al[mt][0] = __float_as_uint(sm[SM_ALO + r0 * ASTR + c0]);
                al[mt][1] = __float_as_uint(sm[SM_ALO + (r0 + 8) * ASTR + c0]);
                al[mt][2] = __float_as_uint(sm[SM_ALO + r0 * ASTR + c0 + 4]);
                al[mt][3] = __float_as_uint(sm[SM_ALO + (r0 + 8) * ASTR + c0 + 4]);
            }
#pragma unroll
            for (int nt = 0; nt < 8; nt++) {
                int n = warpN * 64 + nt * 8 + (lane >> 2);
                int kr = k0 + (lane & 3);
                uint32_t bh[2], bl[2];
                bh[0] = __float_as_uint(sm[SM_BHI + kr * BSTR + n]);
                bh[1] = __float_as_uint(sm[SM_BHI + (kr + 4) * BSTR + n]);
                bl[0] = __float_as_uint(sm[SM_BLO + kr * BSTR + n]);
                bl[1] = __float_as_uint(sm[SM_BLO + (kr + 4) * BSTR + n]);
#pragma unroll
                for (int mt = 0; mt < 2; mt++) {
                    mma_tf32(acc[mt][nt], ah[mt], bh);
                    mma_tf32(acc[mt][nt], ah[mt], bl);
                    mma_tf32(acc[mt][nt], al[mt], bh);
                }
            }
        }
        __syncthreads();
    }

    // ---- epilogue: bias + relu, direct global stores ----
#pragma unroll
    for (int mt = 0; mt < 2; mt++) {
        int row = base + warpM * 32 + mt * 16 + (lane >> 2);
#pragma unroll
        for (int nt = 0; nt < 8; nt++) {
            int col = warpN * 64 + nt * 8 + (lane & 3) * 2;
            float2 bv = *(const float2*)&bias[col];
            if (row < rowlim) {
                float2 o;
                o.x = fmaxf(acc[mt][nt][0] + bv.x, 0.f);
                o.y = fmaxf(acc[mt][nt][1] + bv.y, 0.f);
                *(float2*)&C[(size_t)row * HH + col] = o;
            }
            if (row + 8 < rowlim) {
                float2 o;
                o.x = fmaxf(acc[mt][nt][2] + bv.x, 0.f);
                o.y = fmaxf(acc[mt][nt][3] + bv.y, 0.f);
                *(float2*)&C[(size_t)(row + 8) * HH + col] = o;
            }
        }
    }
}

// ---------------- launch ----------------
extern "C" void kernel_launch(void* const* d_in, const int* in_sizes, int n_in,
                              void* d_out, int out_size) {
    const float* x_patient = (const float*)d_in[0];
    const float* x_concept = (const float*)d_in[1];
    const float* W_p    = (const float*)d_in[2];
    const float* b_p    = (const float*)d_in[3];
    const float* W_c    = (const float*)d_in[4];
    const float* b_c    = (const float*)d_in[5];
    const float* W_root = (const float*)d_in[6];
    const float* b_root = (const float*)d_in[7];
    const float* W_rel  = (const float*)d_in[8];
    const int* src_pc = (const int*)d_in[9];
    const int* dst_pc = (const int*)d_in[10];
    const int* src_cp = (const int*)d_in[11];
    const int* dst_cp = (const int*)d_in[12];
    float* out = (float*)d_out;

    float *buf0, *buf1, *agg, *rcnt, *Bg;
    int *deg, *off, *cur, *csr;
    cudaGetSymbolAddress((void**)&buf0, g_buf0);
    cudaGetSymbolAddress((void**)&buf1, g_buf1);
    cudaGetSymbolAddress((void**)&agg,  g_agg);
    cudaGetSymbolAddress((void**)&rcnt, g_rcnt);
    cudaGetSymbolAddress((void**)&deg,  g_deg);
    cudaGetSymbolAddress((void**)&off,  g_off);
    cudaGetSymbolAddress((void**)&cur,  g_cur);
    cudaGetSymbolAddress((void**)&csr,  g_csr);
    cudaGetSymbolAddress((void**)&Bg,   g_B);

    const int PROJ64_SMEM  = (64  * 128 + 64 * 64 ) * 4;
    const int PROJ128_SMEM = (128 * 128 + 64 * 128) * 4;
    const int LAYER_SMEM   = SM_FLOATS * 4;              // ~71.7 KB
    cudaFuncSetAttribute(proj_kernel<64>,  cudaFuncAttributeMaxDynamicSharedMemorySize, PROJ64_SMEM);
    cudaFuncSetAttribute(proj_kernel<128>, cudaFuncAttributeMaxDynamicSharedMemorySize, PROJ128_SMEM);
    cudaFuncSetAttribute(layer_mma_kernel, cudaFuncAttributeMaxDynamicSharedMemorySize, LAYER_SMEM);

    // ---- CSR build ----
    cudaMemsetAsync(deg, 0, NN * sizeof(int));
    cudaMemsetAsync(cur, 0, NN * sizeof(int));
    deg_kernel<<<(2 * EE + 255) / 256, 256>>>(dst_pc, dst_cp, deg);
    scan_kernel<<<1, 1024>>>(deg, off);
    rcnt_kernel<<<(NN + 255) / 256, 256>>>(deg, rcnt);
    fill_kernel<<<(2 * EE + 255) / 256, 256>>>(src_pc, dst_pc, src_cp, dst_cp, off, cur, csr);

    // ---- weight prep ----
    prepB_kernel<<<(4 * 256 * 128 + 255) / 256, 256>>>(W_root, W_rel, Bg);

    // ---- projections ----
    proj_kernel<64><<<(NPAT + 63) / 64, 256, PROJ64_SMEM>>>(x_patient, W_p, b_p, buf0, NPAT);
    proj_kernel<128><<<(NCON + 63) / 64, 256, PROJ128_SMEM>>>(x_concept, W_c, b_c,
                                                              buf0 + (size_t)NPAT * HH, NCON);

    const int NB_TC = (NPAT + 127) / 128 + (NCON + 127) / 128;  // 391 + 157 = 548
    const int GATHER_BLOCKS = (NN + 7) / 8;

    for (int l = 0; l < LL; l++) {
        const float* in  = (l == 0) ? buf0 : buf1;
        float*       dst = (l == 0) ? buf1 : out;
        gather_kernel<<<GATHER_BLOCKS, 256>>>(in, off, csr, rcnt, agg);
        layer_mma_kernel<<<NB_TC, 256, LAYER_SMEM>>>(in, agg, Bg,
                                                     b_root + (size_t)l * HH, dst, l);
    }
}